// round 2
// baseline (speedup 1.0000x reference)
#include <cuda_runtime.h>
#include <math.h>

// ---------------- problem constants ----------------
#define N_SRC   50000
#define N_DST   50000
#define E_NUM   800000
#define IN_NODE 128
#define OUT_NODE 64
#define NHEAD   4
#define HN      (NHEAD*OUT_NODE)   // 256
#define HE      64                 // NHEAD*OUT_EDGE
#define SLOPE   0.01f
#define OUT_ELEMS (N_DST*OUT_NODE) // 3,200,000

// ---------------- scratch (device globals; allocation-free) ----------------
__device__ __align__(16) float g_hsrc[(size_t)N_SRC * HN];   // 51.2 MB
__device__ __align__(16) float g_fni [(size_t)N_SRC * HE];   // 12.8 MB
__device__ __align__(16) float g_fnj [(size_t)N_DST * HE];   // 12.8 MB
__device__ __align__(16) float g_logit[(size_t)E_NUM * NHEAD];
__device__ __align__(16) float g_a   [(size_t)E_NUM * NHEAD];
__device__ __align__(16) float g_m   [(size_t)N_DST * NHEAD];
__device__ __align__(16) float g_s   [(size_t)N_DST * NHEAD];
__device__ __align__(16) float g_wsum[HE];

// ---------------- helpers ----------------
__device__ __forceinline__ void redAddF4(float4* p, float4 v) {
    asm volatile("red.global.add.v4.f32 [%0], {%1, %2, %3, %4};"
                 :: "l"(__cvta_generic_to_global(p)),
                    "f"(v.x), "f"(v.y), "f"(v.z), "f"(v.w)
                 : "memory");
}

__device__ __forceinline__ void atomicMaxFloat(float* addr, float v) {
    if (v >= 0.f) atomicMax((int*)addr, __float_as_int(v));
    else          atomicMin((unsigned int*)addr, __float_as_uint(v));
}

__device__ __forceinline__ float leaky(float x) {
    return x >= 0.f ? x : SLOPE * x;
}

// ---------------- init: zero out, m=-inf, s=0 ----------------
__global__ void init_kernel(float* __restrict__ out) {
    int i = blockIdx.x * blockDim.x + threadIdx.x;   // exact 3,200,000
    out[i] = 0.f;
    if (i < N_DST * NHEAD) {
        g_m[i] = -INFINITY;
        g_s[i] = 0.f;
    }
}

// ---------------- wsum[c] = sum_k W_fij[k][c]  (efeats = reward broadcast) ---
__global__ void prep_wsum(const float* __restrict__ W_fij) {
    int c = threadIdx.x;   // 64 threads
    float s = 0.f;
#pragma unroll
    for (int k = 0; k < 16; k++) s += W_fij[k * HE + c];
    g_wsum[c] = s;
}

// ---------------- SGEMM: C[M,N] = A[M,K] @ B[K,N] (+bias) ----------------
// BM=128, BN=64, BK=16, TM=TN=8, 128 threads
#define BM 128
#define BN 64
#define BK 16
#define TM 8
#define TN 8

__global__ void __launch_bounds__(128)
sgemm_bias(const float* __restrict__ A, const float* __restrict__ B,
           const float* __restrict__ bias, float* __restrict__ C,
           int M, int N, int K)
{
    __shared__ float As[BK][BM + 4];   // k-major, stride 132
    __shared__ float Bs[BK][BN];

    const int tid = threadIdx.x;
    const int tr  = tid >> 3;   // 0..15 -> rows tr*8..tr*8+7
    const int tc  = tid & 7;    // 0..7  -> cols tc*8..tc*8+7
    const int m0  = blockIdx.x * BM;
    const int n0  = blockIdx.y * BN;

    float acc[TM][TN];
#pragma unroll
    for (int i = 0; i < TM; i++)
#pragma unroll
        for (int j = 0; j < TN; j++) acc[i][j] = 0.f;

    for (int k0 = 0; k0 < K; k0 += BK) {
        // A tile: 128 rows x 16 k  (512 float4), transpose to k-major
#pragma unroll
        for (int t = 0; t < 4; t++) {
            int slot = tid + t * 128;
            int m  = slot >> 2;
            int k4 = slot & 3;
            float4 v = make_float4(0.f, 0.f, 0.f, 0.f);
            int gm = m0 + m;
            if (gm < M)
                v = *(const float4*)(A + (size_t)gm * K + k0 + k4 * 4);
            As[k4 * 4 + 0][m] = v.x;
            As[k4 * 4 + 1][m] = v.y;
            As[k4 * 4 + 2][m] = v.z;
            As[k4 * 4 + 3][m] = v.w;
        }
        // B tile: 16 k x 64 n  (256 float4), direct copy
#pragma unroll
        for (int t = 0; t < 2; t++) {
            int slot = tid + t * 128;
            int k  = slot >> 4;
            int n4 = slot & 15;
            float4 v = *(const float4*)(B + (size_t)(k0 + k) * N + n0 + n4 * 4);
            *(float4*)&Bs[k][n4 * 4] = v;
        }
        __syncthreads();

#pragma unroll
        for (int k = 0; k < BK; k++) {
            float a[TM], b[TN];
#pragma unroll
            for (int i = 0; i < TM; i += 4)
                *(float4*)&a[i] = *(const float4*)&As[k][tr * TM + i];
#pragma unroll
            for (int j = 0; j < TN; j += 4)
                *(float4*)&b[j] = *(const float4*)&Bs[k][tc * TN + j];
#pragma unroll
            for (int i = 0; i < TM; i++)
#pragma unroll
                for (int j = 0; j < TN; j++)
                    acc[i][j] = fmaf(a[i], b[j], acc[i][j]);
        }
        __syncthreads();
    }

#pragma unroll
    for (int i = 0; i < TM; i++) {
        int gm = m0 + tr * TM + i;
        if (gm < M) {
#pragma unroll
            for (int j = 0; j < TN; j += 4) {
                int gn = n0 + tc * TN + j;
                float4 v = make_float4(acc[i][j], acc[i][j + 1],
                                       acc[i][j + 2], acc[i][j + 3]);
                if (bias) {
                    float4 bv = *(const float4*)(bias + gn);
                    v.x += bv.x; v.y += bv.y; v.z += bv.z; v.w += bv.w;
                }
                *(float4*)(C + (size_t)gm * N + gn) = v;
            }
        }
    }
}

// ---------------- stage B: per-edge attention logits + segment max ---------
// 16 threads per edge; grid exact: 800000*16 = 50000 * 256
__global__ void __launch_bounds__(256)
edge_logits(const int* __restrict__ src, const int* __restrict__ dst,
            const float* __restrict__ reward,
            const float* __restrict__ attn, const float* __restrict__ b_e)
{
    int gi   = blockIdx.x * blockDim.x + threadIdx.x;
    int e    = gi >> 4;
    int lane = gi & 15;

    int si = src[e];
    int d  = dst[e];
    float r = reward[e];

    float4 f  = *(const float4*)(g_fni + (size_t)si * HE + lane * 4);
    float4 nj = *(const float4*)(g_fnj + (size_t)d  * HE + lane * 4);
    float4 ws = ((const float4*)g_wsum)[lane];
    float4 be = ((const float4*)b_e)[lane];

    f.x = leaky(f.x + nj.x + r * ws.x + be.x);
    f.y = leaky(f.y + nj.y + r * ws.y + be.y);
    f.z = leaky(f.z + nj.z + r * ws.z + be.z);
    f.w = leaky(f.w + nj.w + r * ws.w + be.w);

    float4 at = ((const float4*)attn)[lane];   // attn[h][16]: lane -> h*16 + q*4
    float p = f.x * at.x + f.y * at.y + f.z * at.z + f.w * at.w;
    p += __shfl_xor_sync(0xffffffffu, p, 1);
    p += __shfl_xor_sync(0xffffffffu, p, 2);

    if ((lane & 3) == 0) {
        int h = lane >> 2;
        g_logit[(size_t)e * NHEAD + h] = p;
        atomicMaxFloat(g_m + (size_t)d * NHEAD + h, p);
    }
}

// ---------------- stage C: a = exp(e - m[dst]); s[dst] += a ----------------
__global__ void __launch_bounds__(256)
edge_exp(const int* __restrict__ dst)
{
    int e = blockIdx.x * blockDim.x + threadIdx.x;   // exact 800000
    int d = dst[e];
    float4 lg = *(const float4*)(g_logit + (size_t)e * NHEAD);
    float4 mm = *(const float4*)(g_m + (size_t)d * NHEAD);
    float4 a;
    a.x = __expf(lg.x - mm.x);
    a.y = __expf(lg.y - mm.y);
    a.z = __expf(lg.z - mm.z);
    a.w = __expf(lg.w - mm.w);
    *(float4*)(g_a + (size_t)e * NHEAD) = a;
    redAddF4((float4*)g_s + d, a);
}

// ---------------- stage D: head-combined weighted aggregation --------------
// out[d,f] += sum_h a_h * h_src[src, h, f]   (64 atomic floats/edge, not 256)
__global__ void __launch_bounds__(256)
edge_agg(const int* __restrict__ src, const int* __restrict__ dst,
         float* __restrict__ out)
{
    int gi   = blockIdx.x * blockDim.x + threadIdx.x;
    int e    = gi >> 4;
    int lane = gi & 15;

    int si = src[e];
    int d  = dst[e];

    float4 av = *(const float4*)(g_a + (size_t)e * NHEAD);
    float4 sv = *(const float4*)(g_s + (size_t)d * NHEAD);
    float a0 = av.x / (sv.x > 0.f ? sv.x : 1.f);
    float a1 = av.y / (sv.y > 0.f ? sv.y : 1.f);
    float a2 = av.z / (sv.z > 0.f ? sv.z : 1.f);
    float a3 = av.w / (sv.w > 0.f ? sv.w : 1.f);

    const float4* hp = (const float4*)(g_hsrc + (size_t)si * HN);
    float4 v0 = hp[lane];
    float4 v1 = hp[16 + lane];
    float4 v2 = hp[32 + lane];
    float4 v3 = hp[48 + lane];

    float4 acc;
    acc.x = a0 * v0.x + a1 * v1.x + a2 * v2.x + a3 * v3.x;
    acc.y = a0 * v0.y + a1 * v1.y + a2 * v2.y + a3 * v3.y;
    acc.z = a0 * v0.z + a1 * v1.z + a2 * v2.z + a3 * v3.z;
    acc.w = a0 * v0.w + a1 * v1.w + a2 * v2.w + a3 * v3.w;

    redAddF4((float4*)out + (size_t)d * 16 + lane, acc);
}

// ---------------- finalize: relu(mean over heads) --------------------------
__global__ void __launch_bounds__(256)
finalize(float* __restrict__ out)
{
    int i = blockIdx.x * blockDim.x + threadIdx.x;   // exact 3,200,000
    out[i] = fmaxf(out[i] * 0.25f, 0.f);
}

// ---------------- launch ----------------
extern "C" void kernel_launch(void* const* d_in, const int* in_sizes, int n_in,
                              void* d_out, int out_size)
{
    const float* nfeats  = (const float*)d_in[0];
    const float* dstf    = (const float*)d_in[1];
    const float* reward  = (const float*)d_in[2];
    const int*   src     = (const int*)  d_in[3];
    const int*   dst     = (const int*)  d_in[4];
    const float* W_ns    = (const float*)d_in[5];
    const float* b_ns    = (const float*)d_in[6];
    const float* W_ni    = (const float*)d_in[7];
    const float* W_nj    = (const float*)d_in[8];
    const float* W_fij   = (const float*)d_in[9];
    const float* attn    = (const float*)d_in[10];
    const float* b_e     = (const float*)d_in[11];
    float* out = (float*)d_out;

    void *p_hsrc, *p_fni, *p_fnj;
    cudaGetSymbolAddress(&p_hsrc, g_hsrc);
    cudaGetSymbolAddress(&p_fni,  g_fni);
    cudaGetSymbolAddress(&p_fnj,  g_fnj);

    init_kernel<<<OUT_ELEMS / 256, 256>>>(out);
    prep_wsum<<<1, 64>>>(W_fij);

    dim3 gA((N_SRC + BM - 1) / BM, HN / BN);   // 391 x 4
    sgemm_bias<<<gA, 128>>>(nfeats, W_ns, b_ns, (float*)p_hsrc, N_SRC, HN, IN_NODE);
    dim3 gB((N_SRC + BM - 1) / BM, 1);         // 391 x 1
    sgemm_bias<<<gB, 128>>>(nfeats, W_ni, nullptr, (float*)p_fni, N_SRC, HE, IN_NODE);
    sgemm_bias<<<gB, 128>>>(dstf,   W_nj, nullptr, (float*)p_fnj, N_DST, HE, IN_NODE);

    edge_logits<<<E_NUM * 16 / 256, 256>>>(src, dst, reward, attn, b_e);
    edge_exp   <<<E_NUM / 256, 256>>>(dst);
    edge_agg   <<<E_NUM * 16 / 256, 256>>>(src, dst, out);
    finalize   <<<OUT_ELEMS / 256, 256>>>(out);
}